// round 15
// baseline (speedup 1.0000x reference)
#include <cuda_runtime.h>
#include <cuda_fp16.h>
#include <cstdint>

#define D_MODEL 1024
#define NHEAD   16
#define HDIM    64
#define BATCH   2
#define SEQ     2048
#define MTOT    (BATCH*SEQ)          // 4096
#define NQKV    (3*D_MODEL)          // 3072

// ---------------- scratch (static device globals; no allocation) ----------
__device__ __half g_qh[BATCH*NHEAD*SEQ*HDIM];    // [B,H,T,Dh]  pre-scaled
__device__ __half g_kh[BATCH*NHEAD*SEQ*HDIM];    // [B,H,T,Dh]
__device__ __half g_vh[BATCH*NHEAD*SEQ*HDIM];    // [B,H,T,Dh]
__device__ __half g_attnh[MTOT*D_MODEL];         // [B,T,C]
__device__ __half g_xh[MTOT*D_MODEL];            // x as half
__device__ __half g_wqkvh[D_MODEL*NQKV];         // w_qkv as half, [K][N] natural
__device__ __half g_wouth[D_MODEL*D_MODEL];      // w_out as half, [K][N] natural

// ---------------- helpers ---------------------------------------------------
__device__ __forceinline__ uint32_t smem_u32(const void* p) {
    uint32_t a;
    asm("{ .reg .u64 t; cvta.to.shared.u64 t, %1; cvt.u32.u64 %0, t; }" : "=r"(a) : "l"(p));
    return a;
}
__device__ __forceinline__ uint32_t h2pack(float lo, float hi) {
    __half2 h = __floats2half2_rn(lo, hi);
    return *(uint32_t*)&h;
}
__device__ __forceinline__ void mma16(float* c,
    uint32_t a0, uint32_t a1, uint32_t a2, uint32_t a3,
    uint32_t b0, uint32_t b1)
{
    asm volatile(
        "mma.sync.aligned.m16n8k16.row.col.f32.f16.f16.f32 "
        "{%0,%1,%2,%3}, {%4,%5,%6,%7}, {%8,%9}, {%0,%1,%2,%3};"
        : "+f"(c[0]), "+f"(c[1]), "+f"(c[2]), "+f"(c[3])
        : "r"(a0), "r"(a1), "r"(a2), "r"(a3), "r"(b0), "r"(b1));
}
__device__ __forceinline__ void ldm_x4(uint32_t* r, uint32_t addr) {
    asm volatile("ldmatrix.sync.aligned.m8n8.x4.shared.b16 {%0,%1,%2,%3}, [%4];"
        : "=r"(r[0]), "=r"(r[1]), "=r"(r[2]), "=r"(r[3]) : "r"(addr));
}
__device__ __forceinline__ void ldm_x4_t(uint32_t* r, uint32_t addr) {
    asm volatile("ldmatrix.sync.aligned.m8n8.x4.trans.shared.b16 {%0,%1,%2,%3}, [%4];"
        : "=r"(r[0]), "=r"(r[1]), "=r"(r[2]), "=r"(r[3]) : "r"(addr));
}
__device__ __forceinline__ void cp16(uint32_t dst, const void* src) {
    asm volatile("cp.async.cg.shared.global [%0], [%1], 16;" :: "r"(dst), "l"(src));
}
#define CP_COMMIT() asm volatile("cp.async.commit_group;" ::: "memory")
#define CP_WAIT(n)  asm volatile("cp.async.wait_group %0;" :: "n"(n) : "memory")

// ===========================================================================
// Merged pre-pass: pure elementwise f32 -> half for x, w_qkv, w_out.
// No transposes (GEMMs consume natural [K][N] weights via trans-ldmatrix).
// Each block: 256 threads x 2 float4 = 2048 elements.
// ===========================================================================
#define XBLK  (MTOT*D_MODEL/2048)       // 2048
#define WQBLK (D_MODEL*NQKV/2048)       // 1536
#define WOBLK (D_MODEL*D_MODEL/2048)    // 512
#define PRE_BLOCKS (XBLK + WQBLK + WOBLK)   // 4096

__global__ __launch_bounds__(256) void prepass_kernel(
    const float* __restrict__ x,
    const float* __restrict__ w_qkv,
    const float* __restrict__ w_out)
{
    int b = blockIdx.x;
    const float4* src;
    uint2* dst;
    if (b < XBLK)            { src = (const float4*)x;     dst = (uint2*)g_xh; }
    else if (b < XBLK+WQBLK) { src = (const float4*)w_qkv; dst = (uint2*)g_wqkvh; b -= XBLK; }
    else                     { src = (const float4*)w_out; dst = (uint2*)g_wouth; b -= XBLK+WQBLK; }
    int i = b*512 + threadIdx.x;
    #pragma unroll
    for (int r = 0; r < 2; r++) {
        float4 v = src[i + r*256];
        dst[i + r*256] = make_uint2(h2pack(v.x, v.y), h2pack(v.z, v.w));
    }
}

// ===========================================================================
// fp16 MMA GEMM (f32 accum): CTA 128x128, 256 threads, warp tile 64x32.
// A row-major [m][k]; B = natural W [k][n], fragments via TRANS ldmatrix.
// K chunk 64, 3-stage cp.async, one sync per chunk.
// Stage: A 128 x 144B (18432) + B 64 x 272B (17408) = 35840B; x3 = 107520B.
// ===========================================================================
#define GA_ROW_B 144
#define GB_ROW_B 272
#define G_A_BYTES (128*GA_ROW_B)            // 18432
#define G_STAGE_BYTES (G_A_BYTES + 64*GB_ROW_B)   // 35840
#define GEMM_SMEM_BYTES (3*G_STAGE_BYTES)   // 107520
#define NCHUNKS (D_MODEL/64)                // 16

__device__ __forceinline__ void gemm_issue(
    uint32_t smem_u, int st,
    const __half* __restrict__ A, const __half* __restrict__ W, int ldW,
    int m0, int n0, int k0, int tid)
{
    uint32_t sa = smem_u + st*G_STAGE_BYTES;
    uint32_t sb = sa + G_A_BYTES;
    // A: 128 rows x 64 halves (128B) each
    const int arow = tid >> 3;     // 0..31 (+32*i)
    const int ac8  = tid & 7;      // 0..7
    #pragma unroll
    for (int i = 0; i < 4; i++) {
        int r = i*32 + arow;
        cp16(sa + r*GA_ROW_B + ac8*16, A + (size_t)(m0+r)*D_MODEL + k0 + ac8*8);
    }
    // B: 64 k-rows x 128 halves (256B) each
    const int brow = tid >> 2;     // 0..63
    const int bc   = tid & 3;      // 0..3
    #pragma unroll
    for (int i = 0; i < 4; i++) {
        cp16(sb + brow*GB_ROW_B + (i*4 + bc)*16,
             W + (size_t)(k0+brow)*ldW + n0 + (i*4 + bc)*8);
    }
}

__device__ __forceinline__ void gemm_tile_h(
    uint32_t smem_u,
    const __half* __restrict__ A, const __half* __restrict__ W, int ldW,
    int m0, int n0, float acc[4][4][4])
{
    const int tid  = threadIdx.x;
    const int lane = tid & 31;
    const int wid  = tid >> 5;
    const int wm   = wid & 1;
    const int wn   = wid >> 1;

    // A fragments (non-trans): tiles (r,k0),(r+8,k0),(r,k8),(r+8,k8)
    const uint32_t aOff = (uint32_t)(wm*64 + (lane & 7) + ((lane >> 3) & 1)*8)*GA_ROW_B
                        + ((lane >> 4) & 1)*16;
    // B fragments (TRANS, source rows = k, cols = n), V-path mapping:
    //   bit3 -> +8 k-rows; bit4 -> +16B n-cols; k-step = +16 rows; n-step = +32B
    const uint32_t bOff = (uint32_t)((lane & 7) + ((lane >> 3) & 1)*8)*GB_ROW_B
                        + ((lane >> 4) & 1)*16 + wn*64;

    gemm_issue(smem_u, 0, A, W, ldW, m0, n0, 0,  tid); CP_COMMIT();
    gemm_issue(smem_u, 1, A, W, ldW, m0, n0, 64, tid); CP_COMMIT();

    for (int s = 0; s < NCHUNKS; s++) {
        CP_WAIT(1);
        __syncthreads();
        if (s + 2 < NCHUNKS) {
            gemm_issue(smem_u, (s+2)%3, A, W, ldW, m0, n0, (s+2)*64, tid);
            CP_COMMIT();
        }
        const uint32_t base  = smem_u + (s%3)*G_STAGE_BYTES;
        const uint32_t bBase = base + G_A_BYTES;

        #pragma unroll
        for (int ks = 0; ks < 4; ks++) {
            uint32_t a[4][4], b[2][4];
            #pragma unroll
            for (int mt = 0; mt < 4; mt++)
                ldm_x4(a[mt], base + aOff + mt*(16*GA_ROW_B) + ks*32);
            #pragma unroll
            for (int np = 0; np < 2; np++)
                ldm_x4_t(b[np], bBase + bOff + ks*(16*GB_ROW_B) + np*32);
            #pragma unroll
            for (int nt = 0; nt < 4; nt++) {
                uint32_t b0 = b[nt >> 1][(nt & 1)*2];
                uint32_t b1 = b[nt >> 1][(nt & 1)*2 + 1];
                #pragma unroll
                for (int mt = 0; mt < 4; mt++)
                    mma16(acc[mt][nt], a[mt][0], a[mt][1], a[mt][2], a[mt][3], b0, b1);
            }
        }
    }
}

// ---- GEMM 1: qkv = x @ w_qkv + b; q/k/v stored coalesced [B,H,T,Dh] --------
__global__ __launch_bounds__(256,2) void qkv_mma_kernel(const float* __restrict__ bias)
{
    extern __shared__ uint32_t smg[];
    uint32_t smem_u = smem_u32(smg);

    const int n0 = blockIdx.x * 128;
    const int m0 = blockIdx.y * 128;
    const int lane = threadIdx.x & 31;
    const int wid  = threadIdx.x >> 5;
    const int wm = wid & 1, wn = wid >> 1;
    const int lq = lane & 3, gq = lane >> 2;

    float acc[4][4][4];
    #pragma unroll
    for (int i = 0; i < 4; i++)
        #pragma unroll
        for (int j = 0; j < 4; j++)
            #pragma unroll
            for (int k = 0; k < 4; k++) acc[i][j][k] = 0.f;

    gemm_tile_h(smem_u, g_xh, g_wqkvh, NQKV, m0, n0, acc);

    const float QSCALE = 0.125f * 1.4426950408889634f;

    #pragma unroll
    for (int mt = 0; mt < 4; mt++) {
        int rbase = m0 + wm*64 + mt*16 + gq;
        #pragma unroll
        for (int half_ = 0; half_ < 2; half_++) {
            int row = rbase + half_*8;
            int bb = row >> 11;
            int t  = row & 2047;
            #pragma unroll
            for (int nt = 0; nt < 4; nt++) {
                int n = n0 + wn*32 + nt*8 + lq*2;
                float v0 = acc[mt][nt][half_*2+0] + __ldg(bias + n);
                float v1 = acc[mt][nt][half_*2+1] + __ldg(bias + n + 1);
                int sec = n >> 10;
                int h   = (n >> 6) & 15;
                int d   = n & 63;
                int bh  = bb*NHEAD + h;
                size_t idx = ((size_t)bh*SEQ + t)*HDIM + d;
                if (sec == 0) {
                    *(uint32_t*)&g_qh[idx] = h2pack(v0*QSCALE, v1*QSCALE);
                } else if (sec == 1) {
                    *(uint32_t*)&g_kh[idx] = h2pack(v0, v1);
                } else {
                    *(uint32_t*)&g_vh[idx] = h2pack(v0, v1);
                }
            }
        }
    }
}

// ---- GEMM 3: out = attn @ w_out + b (f32 output) ----------------------------
__global__ __launch_bounds__(256,2) void out_mma_kernel(
    const float* __restrict__ bias, float* __restrict__ out)
{
    extern __shared__ uint32_t smg[];
    uint32_t smem_u = smem_u32(smg);

    const int n0 = blockIdx.x * 128;
    const int m0 = blockIdx.y * 128;
    const int lane = threadIdx.x & 31;
    const int wid  = threadIdx.x >> 5;
    const int wm = wid & 1, wn = wid >> 1;
    const int lq = lane & 3, gq = lane >> 2;

    float acc[4][4][4];
    #pragma unroll
    for (int i = 0; i < 4; i++)
        #pragma unroll
        for (int j = 0; j < 4; j++)
            #pragma unroll
            for (int k = 0; k < 4; k++) acc[i][j][k] = 0.f;

    gemm_tile_h(smem_u, g_attnh, g_wouth, D_MODEL, m0, n0, acc);

    #pragma unroll
    for (int mt = 0; mt < 4; mt++) {
        int rbase = m0 + wm*64 + mt*16 + gq;
        #pragma unroll
        for (int half_ = 0; half_ < 2; half_++) {
            int row = rbase + half_*8;
            #pragma unroll
            for (int nt = 0; nt < 4; nt++) {
                int n = n0 + wn*32 + nt*8 + lq*2;
                float v0 = acc[mt][nt][half_*2+0] + __ldg(bias + n);
                float v1 = acc[mt][nt][half_*2+1] + __ldg(bias + n + 1);
                *(float2*)&out[(size_t)row*D_MODEL + n] = make_float2(v0, v1);
            }
        }
    }
}

// ===========================================================================
// Flash attention, fp16 MMA (f32 accum). K non-trans; V trans (both [c][d]).
#define QTILE 128
#define KTILE 64
#define KV_ROW_B 144
#define FL_BUF_BYTES 18432
#define FLASH_SMEM_BYTES (3*FL_BUF_BYTES)     // 55296

__device__ __forceinline__ void flash_issue_kv(
    uint32_t smem_u, int bufidx, int kt,
    const __half* __restrict__ kb, const __half* __restrict__ vb, int tid)
{
    uint32_t kdst = smem_u + bufidx*FL_BUF_BYTES;
    uint32_t vdst = kdst + 64*KV_ROW_B;
    #pragma unroll
    for (int i = 0; i < 2; i++) {
        int idx = tid + i*256;
        int row = idx >> 3, c8 = idx & 7;
        cp16(kdst + row*KV_ROW_B + c8*16,
             kb + ((size_t)kt*KTILE + row)*HDIM + c8*8);
    }
    #pragma unroll
    for (int i = 0; i < 2; i++) {
        int idx = tid + i*256;
        int row = idx >> 3, c8 = idx & 7;
        cp16(vdst + row*KV_ROW_B + c8*16,
             vb + ((size_t)kt*KTILE + row)*HDIM + c8*8);
    }
}

__global__ __launch_bounds__(256,2) void flash_mma_kernel()
{
    extern __shared__ uint32_t smu[];
    uint32_t smem_u = smem_u32(smu);

    const int tid  = threadIdx.x;
    const int lane = tid & 31;
    const int wid  = tid >> 5;
    const int lq   = lane & 3;
    const int gq   = lane >> 2;

    const int qt = blockIdx.x;
    const int h  = blockIdx.y;
    const int bb = blockIdx.z;
    const int bh = bb*NHEAD + h;

    const __half* qb = g_qh + ((size_t)bh*SEQ + qt*QTILE)*HDIM;
    const __half* kb = g_kh + (size_t)bh*SEQ*HDIM;
    const __half* vb = g_vh + (size_t)bh*SEQ*HDIM;

    flash_issue_kv(smem_u, 0, 0, kb, vb, tid); CP_COMMIT();
    flash_issue_kv(smem_u, 1, 1, kb, vb, tid); CP_COMMIT();

    const int row0 = wid*16 + gq;
    const int row1 = row0 + 8;

    const uint32_t bOff = (uint32_t)((lane & 7) + ((lane >> 4) & 1)*8)*KV_ROW_B
                        + ((lane >> 3) & 1)*16;
    const uint32_t vOff = (uint32_t)((lane & 7) + ((lane >> 3) & 1)*8)*KV_ROW_B
                        + ((lane >> 4) & 1)*16;

    const uint32_t* qu = (const uint32_t*)qb;
    uint32_t qa[4][4];
    #pragma unroll
    for (int kk = 0; kk < 4; kk++) {
        qa[kk][0] = qu[ row0*32 + kk*8 + lq    ];
        qa[kk][1] = qu[ row1*32 + kk*8 + lq    ];
        qa[kk][2] = qu[ row0*32 + kk*8 + lq + 4];
        qa[kk][3] = qu[ row1*32 + kk*8 + lq + 4];
    }

    float m0 = -1e30f, m1 = -1e30f, l0 = 0.f, l1 = 0.f;
    float o[8][4];
    #pragma unroll
    for (int i = 0; i < 8; i++)
        #pragma unroll
        for (int j = 0; j < 4; j++) o[i][j] = 0.f;

    for (int kt = 0; kt < SEQ/KTILE; kt++) {
        CP_WAIT(1);
        __syncthreads();
        if (kt + 2 < SEQ/KTILE) {
            flash_issue_kv(smem_u, (kt+2)%3, kt+2, kb, vb, tid);
            CP_COMMIT();
        }
        const uint32_t kBase = smem_u + (kt%3)*FL_BUF_BYTES;
        const uint32_t vBase = kBase + 64*KV_ROW_B;

        float s[8][4];
        #pragma unroll
        for (int nt = 0; nt < 8; nt++)
            #pragma unroll
            for (int j = 0; j < 4; j++) s[nt][j] = 0.f;

        #pragma unroll
        for (int kk = 0; kk < 4; kk++) {
            uint32_t b[4][4];
            #pragma unroll
            for (int np = 0; np < 4; np++)
                ldm_x4(b[np], kBase + bOff + np*(16*KV_ROW_B) + kk*32);
            #pragma unroll
            for (int nt = 0; nt < 8; nt++) {
                uint32_t b0 = b[nt >> 1][(nt & 1)*2];
                uint32_t b1 = b[nt >> 1][(nt & 1)*2 + 1];
                mma16(s[nt], qa[kk][0], qa[kk][1], qa[kk][2], qa[kk][3], b0, b1);
            }
        }

        float mt0 = -1e30f, mt1 = -1e30f;
        #pragma unroll
        for (int nt = 0; nt < 8; nt++) {
            mt0 = fmaxf(mt0, fmaxf(s[nt][0], s[nt][1]));
            mt1 = fmaxf(mt1, fmaxf(s[nt][2], s[nt][3]));
        }
        mt0 = fmaxf(mt0, __shfl_xor_sync(0xffffffffu, mt0, 1));
        mt0 = fmaxf(mt0, __shfl_xor_sync(0xffffffffu, mt0, 2));
        mt1 = fmaxf(mt1, __shfl_xor_sync(0xffffffffu, mt1, 1));
        mt1 = fmaxf(mt1, __shfl_xor_sync(0xffffffffu, mt1, 2));

        float mn0 = fmaxf(m0, mt0);
        float mn1 = fmaxf(m1, mt1);
        float corr0 = exp2f(m0 - mn0);
        float corr1 = exp2f(m1 - mn1);
        m0 = mn0; m1 = mn1;

        float p[8][4];
        float sum0 = 0.f, sum1 = 0.f;
        #pragma unroll
        for (int nt = 0; nt < 8; nt++) {
            p[nt][0] = exp2f(s[nt][0] - mn0);
            p[nt][1] = exp2f(s[nt][1] - mn0);
            p[nt][2] = exp2f(s[nt][2] - mn1);
            p[nt][3] = exp2f(s[nt][3] - mn1);
            sum0 += p[nt][0] + p[nt][1];
            sum1 += p[nt][2] + p[nt][3];
        }
        sum0 += __shfl_xor_sync(0xffffffffu, sum0, 1);
        sum0 += __shfl_xor_sync(0xffffffffu, sum0, 2);
        sum1 += __shfl_xor_sync(0xffffffffu, sum1, 1);
        sum1 += __shfl_xor_sync(0xffffffffu, sum1, 2);
        l0 = l0*corr0 + sum0;
        l1 = l1*corr1 + sum1;

        #pragma unroll
        for (int nt = 0; nt < 8; nt++) {
            o[nt][0] *= corr0; o[nt][1] *= corr0;
            o[nt][2] *= corr1; o[nt][3] *= corr1;
        }

        #pragma unroll
        for (int kk = 0; kk < 4; kk++) {
            uint32_t a0 = h2pack(p[2*kk  ][0], p[2*kk  ][1]);
            uint32_t a1 = h2pack(p[2*kk  ][2], p[2*kk  ][3]);
            uint32_t a2 = h2pack(p[2*kk+1][0], p[2*kk+1][1]);
            uint32_t a3 = h2pack(p[2*kk+1][2], p[2*kk+1][3]);
            uint32_t b[4][4];
            #pragma unroll
            for (int np = 0; np < 4; np++)
                ldm_x4_t(b[np], vBase + vOff + kk*(16*KV_ROW_B) + np*32);
            #pragma unroll
            for (int nt = 0; nt < 8; nt++) {
                uint32_t b0 = b[nt >> 1][(nt & 1)*2];
                uint32_t b1 = b[nt >> 1][(nt & 1)*2 + 1];
                mma16(o[nt], a0, a1, a2, a3, b0, b1);
            }
        }
    }

    float inv0 = 1.0f / l0;
    float inv1 = 1.0f / l1;
    #pragma unroll
    for (int nt = 0; nt < 8; nt++) {
        int d = nt*8 + lq*2;
        size_t r0g = (size_t)(bb*SEQ + qt*QTILE + row0)*D_MODEL + h*64 + d;
        size_t r1g = (size_t)(bb*SEQ + qt*QTILE + row1)*D_MODEL + h*64 + d;
        *(uint32_t*)&g_attnh[r0g] = h2pack(o[nt][0]*inv0, o[nt][1]*inv0);
        *(uint32_t*)&g_attnh[r1g] = h2pack(o[nt][2]*inv1, o[nt][3]*inv1);
    }
}

// ===========================================================================
extern "C" void kernel_launch(void* const* d_in, const int* in_sizes, int n_in,
                              void* d_out, int out_size)
{
    const float* x     = (const float*)d_in[0];
    const float* w_qkv = (const float*)d_in[1];
    const float* b_qkv = (const float*)d_in[2];
    const float* w_out = (const float*)d_in[3];
    const float* b_out = (const float*)d_in[4];
    float* out = (float*)d_out;

    (void)in_sizes; (void)n_in; (void)out_size;

    cudaFuncSetAttribute(qkv_mma_kernel,
                         cudaFuncAttributeMaxDynamicSharedMemorySize, GEMM_SMEM_BYTES);
    cudaFuncSetAttribute(out_mma_kernel,
                         cudaFuncAttributeMaxDynamicSharedMemorySize, GEMM_SMEM_BYTES);
    cudaFuncSetAttribute(flash_mma_kernel,
                         cudaFuncAttributeMaxDynamicSharedMemorySize, FLASH_SMEM_BYTES);

    // 0) merged elementwise pre-pass (no transposes)
    prepass_kernel<<<PRE_BLOCKS, 256>>>(x, w_qkv, w_out);

    // 1) QKV GEMM (B via trans-ldmatrix on natural weights)
    {
        dim3 grid(NQKV/128, MTOT/128);
        qkv_mma_kernel<<<grid, 256, GEMM_SMEM_BYTES>>>(b_qkv);
    }
    // 2) flash attention
    {
        dim3 grid(SEQ/QTILE, NHEAD, BATCH);
        flash_mma_kernel<<<grid, 256, FLASH_SMEM_BYTES>>>();
    }
    // 3) out GEMM
    {
        dim3 grid(D_MODEL/128, MTOT/128);
        out_mma_kernel<<<grid, 256, GEMM_SMEM_BYTES>>>(b_out, out);
    }
}

// round 16
// speedup vs baseline: 1.0175x; 1.0175x over previous
#include <cuda_runtime.h>
#include <cuda_fp16.h>
#include <cstdint>

#define D_MODEL 1024
#define NHEAD   16
#define HDIM    64
#define BATCH   2
#define SEQ     2048
#define MTOT    (BATCH*SEQ)          // 4096
#define NQKV    (3*D_MODEL)          // 3072

// ---------------- scratch (static device globals; no allocation) ----------
__device__ __half g_qh[BATCH*NHEAD*SEQ*HDIM];    // [B,H,T,Dh]  pre-scaled
__device__ __half g_kh[BATCH*NHEAD*SEQ*HDIM];    // [B,H,T,Dh]
__device__ __half g_vh[BATCH*NHEAD*SEQ*HDIM];    // [B,H,T,Dh]
__device__ __half g_attnh[MTOT*D_MODEL];         // [B,T,C]
__device__ __half g_xh[MTOT*D_MODEL];            // x as half
__device__ __half g_wqkvT[NQKV*D_MODEL];         // w_qkv^T as half
__device__ __half g_woutT[D_MODEL*D_MODEL];      // w_out^T as half

// ---------------- helpers ---------------------------------------------------
__device__ __forceinline__ uint32_t smem_u32(const void* p) {
    uint32_t a;
    asm("{ .reg .u64 t; cvta.to.shared.u64 t, %1; cvt.u32.u64 %0, t; }" : "=r"(a) : "l"(p));
    return a;
}
__device__ __forceinline__ uint32_t h2pack(float lo, float hi) {
    __half2 h = __floats2half2_rn(lo, hi);
    return *(uint32_t*)&h;
}
__device__ __forceinline__ void mma16(float* c,
    uint32_t a0, uint32_t a1, uint32_t a2, uint32_t a3,
    uint32_t b0, uint32_t b1)
{
    asm volatile(
        "mma.sync.aligned.m16n8k16.row.col.f32.f16.f16.f32 "
        "{%0,%1,%2,%3}, {%4,%5,%6,%7}, {%8,%9}, {%0,%1,%2,%3};"
        : "+f"(c[0]), "+f"(c[1]), "+f"(c[2]), "+f"(c[3])
        : "r"(a0), "r"(a1), "r"(a2), "r"(a3), "r"(b0), "r"(b1));
}
__device__ __forceinline__ void ldm_x4(uint32_t* r, uint32_t addr) {
    asm volatile("ldmatrix.sync.aligned.m8n8.x4.shared.b16 {%0,%1,%2,%3}, [%4];"
        : "=r"(r[0]), "=r"(r[1]), "=r"(r[2]), "=r"(r[3]) : "r"(addr));
}
__device__ __forceinline__ void ldm_x4_t(uint32_t* r, uint32_t addr) {
    asm volatile("ldmatrix.sync.aligned.m8n8.x4.trans.shared.b16 {%0,%1,%2,%3}, [%4];"
        : "=r"(r[0]), "=r"(r[1]), "=r"(r[2]), "=r"(r[3]) : "r"(addr));
}
__device__ __forceinline__ void cp16(uint32_t dst, const void* src) {
    asm volatile("cp.async.cg.shared.global [%0], [%1], 16;" :: "r"(dst), "l"(src));
}
#define CP_COMMIT() asm volatile("cp.async.commit_group;" ::: "memory")
#define CP_WAIT(n)  asm volatile("cp.async.wait_group %0;" :: "n"(n) : "memory")

// ===========================================================================
// Merged pre-pass: x->half (elementwise), w_qkv^T->half, w_out^T->half.
// Block ranges:
//   [0, XBLK)            : x cvt (each thread converts 4 float4)
//   [XBLK, XBLK+QT)      : w_qkv transpose tiles (96 x 32)
//   [XBLK+QT, +OT)       : w_out transpose tiles (32 x 32)
// ===========================================================================
#define XBLK 1024                      // (4096*1024/4) / 256 / 4
#define QT_X 96
#define QT_Y 32
#define OT_X 32
#define OT_Y 32
#define PRE_BLOCKS (XBLK + QT_X*QT_Y + OT_X*OT_Y)   // 5120

__global__ __launch_bounds__(256) void prepass_kernel(
    const float* __restrict__ x,
    const float* __restrict__ w_qkv,
    const float* __restrict__ w_out)
{
    __shared__ float t[32][33];
    int b = blockIdx.x;
    if (b < XBLK) {
        const float4* src = (const float4*)x;
        uint2* dst = (uint2*)g_xh;
        int i = b*1024 + threadIdx.x;
        #pragma unroll
        for (int r = 0; r < 4; r++) {
            float4 v = src[i + r*256];
            dst[i + r*256] = make_uint2(h2pack(v.x, v.y), h2pack(v.z, v.w));
        }
        return;
    }
    const float* src;
    __half* dst;
    int bx, by, R, C;
    if (b < XBLK + QT_X*QT_Y) {
        int tb = b - XBLK;
        bx = (tb % QT_X) * 32; by = (tb / QT_X) * 32;
        src = w_qkv; dst = g_wqkvT; R = D_MODEL; C = NQKV;
    } else {
        int tb = b - XBLK - QT_X*QT_Y;
        bx = (tb % OT_X) * 32; by = (tb / OT_X) * 32;
        src = w_out; dst = g_woutT; R = D_MODEL; C = D_MODEL;
    }
    int tx = threadIdx.x & 31;
    int ty = threadIdx.x >> 5;
    #pragma unroll
    for (int i = 0; i < 32; i += 8)
        t[ty + i][tx] = src[(size_t)(by + ty + i)*C + bx + tx];
    __syncthreads();
    #pragma unroll
    for (int i = 0; i < 32; i += 8)
        dst[(size_t)(bx + ty + i)*R + by + tx] = __float2half(t[tx][ty + i]);
}

// ===========================================================================
// fp16 MMA GEMM (f32 accum): CTA 128x128, 256 threads, warp tile 64x32.
// A row-major [m][k]; B = W^T [n][k] (pre-transposed). Non-trans ldmatrix.
// K chunk 64, 3-stage cp.async, one sync per chunk.
// ===========================================================================
#define G_ROW_B 144
#define G_STAGE_BYTES 36864
#define GEMM_SMEM_BYTES (3*G_STAGE_BYTES)   // 110592
#define NCHUNKS (D_MODEL/64)                // 16

__device__ __forceinline__ void gemm_issue(
    uint32_t smem_u, int st,
    const __half* __restrict__ A, const __half* __restrict__ B,
    int m0, int n0, int k0, int tid)
{
    uint32_t sa = smem_u + st*G_STAGE_BYTES;
    uint32_t sb = sa + 128*G_ROW_B;
    const int row = tid >> 3;
    const int c8  = tid & 7;
    #pragma unroll
    for (int i = 0; i < 4; i++) {
        int r = i*32 + row;
        cp16(sa + r*G_ROW_B + c8*16, A + (size_t)(m0+r)*D_MODEL + k0 + c8*8);
    }
    #pragma unroll
    for (int i = 0; i < 4; i++) {
        int r = i*32 + row;
        cp16(sb + r*G_ROW_B + c8*16, B + (size_t)(n0+r)*D_MODEL + k0 + c8*8);
    }
}

__device__ __forceinline__ void gemm_tile_h(
    uint32_t smem_u,
    const __half* __restrict__ A, const __half* __restrict__ B,
    int m0, int n0, float acc[4][4][4])
{
    const int tid  = threadIdx.x;
    const int lane = tid & 31;
    const int wid  = tid >> 5;
    const int wm   = wid & 1;
    const int wn   = wid >> 1;

    const uint32_t aOff = (uint32_t)(wm*64 + (lane & 7) + ((lane >> 3) & 1)*8)*G_ROW_B
                        + ((lane >> 4) & 1)*16;
    const uint32_t bOff = 128*G_ROW_B
                        + (uint32_t)(wn*32 + (lane & 7) + ((lane >> 4) & 1)*8)*G_ROW_B
                        + ((lane >> 3) & 1)*16;

    gemm_issue(smem_u, 0, A, B, m0, n0, 0,  tid); CP_COMMIT();
    gemm_issue(smem_u, 1, A, B, m0, n0, 64, tid); CP_COMMIT();

    for (int s = 0; s < NCHUNKS; s++) {
        CP_WAIT(1);
        __syncthreads();
        if (s + 2 < NCHUNKS) {
            gemm_issue(smem_u, (s+2)%3, A, B, m0, n0, (s+2)*64, tid);
            CP_COMMIT();
        }
        const uint32_t base = smem_u + (s%3)*G_STAGE_BYTES;

        #pragma unroll
        for (int ks = 0; ks < 4; ks++) {
            uint32_t a[4][4], b[2][4];
            #pragma unroll
            for (int mt = 0; mt < 4; mt++)
                ldm_x4(a[mt], base + aOff + mt*(16*G_ROW_B) + ks*32);
            #pragma unroll
            for (int np = 0; np < 2; np++)
                ldm_x4(b[np], base + bOff + np*(16*G_ROW_B) + ks*32);
            #pragma unroll
            for (int nt = 0; nt < 4; nt++) {
                uint32_t b0 = b[nt >> 1][(nt & 1)*2];
                uint32_t b1 = b[nt >> 1][(nt & 1)*2 + 1];
                #pragma unroll
                for (int mt = 0; mt < 4; mt++)
                    mma16(acc[mt][nt], a[mt][0], a[mt][1], a[mt][2], a[mt][3], b0, b1);
            }
        }
    }
}

// ---- GEMM 1: qkv = x @ w_qkv + b; q/k/v stored coalesced [B,H,T,Dh] --------
__global__ __launch_bounds__(256,2) void qkv_mma_kernel(const float* __restrict__ bias)
{
    extern __shared__ uint32_t smg[];
    uint32_t smem_u = smem_u32(smg);

    const int n0 = blockIdx.x * 128;
    const int m0 = blockIdx.y * 128;
    const int lane = threadIdx.x & 31;
    const int wid  = threadIdx.x >> 5;
    const int wm = wid & 1, wn = wid >> 1;
    const int lq = lane & 3, gq = lane >> 2;

    float acc[4][4][4];
    #pragma unroll
    for (int i = 0; i < 4; i++)
        #pragma unroll
        for (int j = 0; j < 4; j++)
            #pragma unroll
            for (int k = 0; k < 4; k++) acc[i][j][k] = 0.f;

    gemm_tile_h(smem_u, g_xh, g_wqkvT, m0, n0, acc);

    const float QSCALE = 0.125f * 1.4426950408889634f;

    #pragma unroll
    for (int mt = 0; mt < 4; mt++) {
        int rbase = m0 + wm*64 + mt*16 + gq;
        #pragma unroll
        for (int half_ = 0; half_ < 2; half_++) {
            int row = rbase + half_*8;
            int bb = row >> 11;
            int t  = row & 2047;
            #pragma unroll
            for (int nt = 0; nt < 4; nt++) {
                int n = n0 + wn*32 + nt*8 + lq*2;
                float v0 = acc[mt][nt][half_*2+0] + __ldg(bias + n);
                float v1 = acc[mt][nt][half_*2+1] + __ldg(bias + n + 1);
                int sec = n >> 10;
                int h   = (n >> 6) & 15;
                int d   = n & 63;
                int bh  = bb*NHEAD + h;
                size_t idx = ((size_t)bh*SEQ + t)*HDIM + d;
                if (sec == 0) {
                    *(uint32_t*)&g_qh[idx] = h2pack(v0*QSCALE, v1*QSCALE);
                } else if (sec == 1) {
                    *(uint32_t*)&g_kh[idx] = h2pack(v0, v1);
                } else {
                    *(uint32_t*)&g_vh[idx] = h2pack(v0, v1);
                }
            }
        }
    }
}

// ---- GEMM 3: out = attn @ w_out + b (f32 output) ----------------------------
__global__ __launch_bounds__(256,2) void out_mma_kernel(
    const float* __restrict__ bias, float* __restrict__ out)
{
    extern __shared__ uint32_t smg[];
    uint32_t smem_u = smem_u32(smg);

    const int n0 = blockIdx.x * 128;
    const int m0 = blockIdx.y * 128;
    const int lane = threadIdx.x & 31;
    const int wid  = threadIdx.x >> 5;
    const int wm = wid & 1, wn = wid >> 1;
    const int lq = lane & 3, gq = lane >> 2;

    float acc[4][4][4];
    #pragma unroll
    for (int i = 0; i < 4; i++)
        #pragma unroll
        for (int j = 0; j < 4; j++)
            #pragma unroll
            for (int k = 0; k < 4; k++) acc[i][j][k] = 0.f;

    gemm_tile_h(smem_u, g_attnh, g_woutT, m0, n0, acc);

    #pragma unroll
    for (int mt = 0; mt < 4; mt++) {
        int rbase = m0 + wm*64 + mt*16 + gq;
        #pragma unroll
        for (int half_ = 0; half_ < 2; half_++) {
            int row = rbase + half_*8;
            #pragma unroll
            for (int nt = 0; nt < 4; nt++) {
                int n = n0 + wn*32 + nt*8 + lq*2;
                float v0 = acc[mt][nt][half_*2+0] + __ldg(bias + n);
                float v1 = acc[mt][nt][half_*2+1] + __ldg(bias + n + 1);
                *(float2*)&out[(size_t)row*D_MODEL + n] = make_float2(v0, v1);
            }
        }
    }
}

// ===========================================================================
// Flash attention, fp16 MMA (f32 accum). K non-trans; V trans (both [c][d]).
#define QTILE 128
#define KTILE 64
#define KV_ROW_B 144
#define FL_BUF_BYTES 18432
#define FLASH_SMEM_BYTES (3*FL_BUF_BYTES)     // 55296

__device__ __forceinline__ void flash_issue_kv(
    uint32_t smem_u, int bufidx, int kt,
    const __half* __restrict__ kb, const __half* __restrict__ vb, int tid)
{
    uint32_t kdst = smem_u + bufidx*FL_BUF_BYTES;
    uint32_t vdst = kdst + 64*KV_ROW_B;
    #pragma unroll
    for (int i = 0; i < 2; i++) {
        int idx = tid + i*256;
        int row = idx >> 3, c8 = idx & 7;
        cp16(kdst + row*KV_ROW_B + c8*16,
             kb + ((size_t)kt*KTILE + row)*HDIM + c8*8);
    }
    #pragma unroll
    for (int i = 0; i < 2; i++) {
        int idx = tid + i*256;
        int row = idx >> 3, c8 = idx & 7;
        cp16(vdst + row*KV_ROW_B + c8*16,
             vb + ((size_t)kt*KTILE + row)*HDIM + c8*8);
    }
}

__global__ __launch_bounds__(256,2) void flash_mma_kernel()
{
    extern __shared__ uint32_t smu[];
    uint32_t smem_u = smem_u32(smu);

    const int tid  = threadIdx.x;
    const int lane = tid & 31;
    const int wid  = tid >> 5;
    const int lq   = lane & 3;
    const int gq   = lane >> 2;

    const int qt = blockIdx.x;
    const int h  = blockIdx.y;
    const int bb = blockIdx.z;
    const int bh = bb*NHEAD + h;

    const __half* qb = g_qh + ((size_t)bh*SEQ + qt*QTILE)*HDIM;
    const __half* kb = g_kh + (size_t)bh*SEQ*HDIM;
    const __half* vb = g_vh + (size_t)bh*SEQ*HDIM;

    flash_issue_kv(smem_u, 0, 0, kb, vb, tid); CP_COMMIT();
    flash_issue_kv(smem_u, 1, 1, kb, vb, tid); CP_COMMIT();

    const int row0 = wid*16 + gq;
    const int row1 = row0 + 8;

    const uint32_t bOff = (uint32_t)((lane & 7) + ((lane >> 4) & 1)*8)*KV_ROW_B
                        + ((lane >> 3) & 1)*16;
    const uint32_t vOff = (uint32_t)((lane & 7) + ((lane >> 3) & 1)*8)*KV_ROW_B
                        + ((lane >> 4) & 1)*16;

    const uint32_t* qu = (const uint32_t*)qb;
    uint32_t qa[4][4];
    #pragma unroll
    for (int kk = 0; kk < 4; kk++) {
        qa[kk][0] = qu[ row0*32 + kk*8 + lq    ];
        qa[kk][1] = qu[ row1*32 + kk*8 + lq    ];
        qa[kk][2] = qu[ row0*32 + kk*8 + lq + 4];
        qa[kk][3] = qu[ row1*32 + kk*8 + lq + 4];
    }

    float m0 = -1e30f, m1 = -1e30f, l0 = 0.f, l1 = 0.f;
    float o[8][4];
    #pragma unroll
    for (int i = 0; i < 8; i++)
        #pragma unroll
        for (int j = 0; j < 4; j++) o[i][j] = 0.f;

    for (int kt = 0; kt < SEQ/KTILE; kt++) {
        CP_WAIT(1);
        __syncthreads();
        if (kt + 2 < SEQ/KTILE) {
            flash_issue_kv(smem_u, (kt+2)%3, kt+2, kb, vb, tid);
            CP_COMMIT();
        }
        const uint32_t kBase = smem_u + (kt%3)*FL_BUF_BYTES;
        const uint32_t vBase = kBase + 64*KV_ROW_B;

        float s[8][4];
        #pragma unroll
        for (int nt = 0; nt < 8; nt++)
            #pragma unroll
            for (int j = 0; j < 4; j++) s[nt][j] = 0.f;

        #pragma unroll
        for (int kk = 0; kk < 4; kk++) {
            uint32_t b[4][4];
            #pragma unroll
            for (int np = 0; np < 4; np++)
                ldm_x4(b[np], kBase + bOff + np*(16*KV_ROW_B) + kk*32);
            #pragma unroll
            for (int nt = 0; nt < 8; nt++) {
                uint32_t b0 = b[nt >> 1][(nt & 1)*2];
                uint32_t b1 = b[nt >> 1][(nt & 1)*2 + 1];
                mma16(s[nt], qa[kk][0], qa[kk][1], qa[kk][2], qa[kk][3], b0, b1);
            }
        }

        float mt0 = -1e30f, mt1 = -1e30f;
        #pragma unroll
        for (int nt = 0; nt < 8; nt++) {
            mt0 = fmaxf(mt0, fmaxf(s[nt][0], s[nt][1]));
            mt1 = fmaxf(mt1, fmaxf(s[nt][2], s[nt][3]));
        }
        mt0 = fmaxf(mt0, __shfl_xor_sync(0xffffffffu, mt0, 1));
        mt0 = fmaxf(mt0, __shfl_xor_sync(0xffffffffu, mt0, 2));
        mt1 = fmaxf(mt1, __shfl_xor_sync(0xffffffffu, mt1, 1));
        mt1 = fmaxf(mt1, __shfl_xor_sync(0xffffffffu, mt1, 2));

        float mn0 = fmaxf(m0, mt0);
        float mn1 = fmaxf(m1, mt1);
        float corr0 = exp2f(m0 - mn0);
        float corr1 = exp2f(m1 - mn1);
        m0 = mn0; m1 = mn1;

        float p[8][4];
        float sum0 = 0.f, sum1 = 0.f;
        #pragma unroll
        for (int nt = 0; nt < 8; nt++) {
            p[nt][0] = exp2f(s[nt][0] - mn0);
            p[nt][1] = exp2f(s[nt][1] - mn0);
            p[nt][2] = exp2f(s[nt][2] - mn1);
            p[nt][3] = exp2f(s[nt][3] - mn1);
            sum0 += p[nt][0] + p[nt][1];
            sum1 += p[nt][2] + p[nt][3];
        }
        sum0 += __shfl_xor_sync(0xffffffffu, sum0, 1);
        sum0 += __shfl_xor_sync(0xffffffffu, sum0, 2);
        sum1 += __shfl_xor_sync(0xffffffffu, sum1, 1);
        sum1 += __shfl_xor_sync(0xffffffffu, sum1, 2);
        l0 = l0*corr0 + sum0;
        l1 = l1*corr1 + sum1;

        #pragma unroll
        for (int nt = 0; nt < 8; nt++) {
            o[nt][0] *= corr0; o[nt][1] *= corr0;
            o[nt][2] *= corr1; o[nt][3] *= corr1;
        }

        #pragma unroll
        for (int kk = 0; kk < 4; kk++) {
            uint32_t a0 = h2pack(p[2*kk  ][0], p[2*kk  ][1]);
            uint32_t a1 = h2pack(p[2*kk  ][2], p[2*kk  ][3]);
            uint32_t a2 = h2pack(p[2*kk+1][0], p[2*kk+1][1]);
            uint32_t a3 = h2pack(p[2*kk+1][2], p[2*kk+1][3]);
            uint32_t b[4][4];
            #pragma unroll
            for (int np = 0; np < 4; np++)
                ldm_x4_t(b[np], vBase + vOff + kk*(16*KV_ROW_B) + np*32);
            #pragma unroll
            for (int nt = 0; nt < 8; nt++) {
                uint32_t b0 = b[nt >> 1][(nt & 1)*2];
                uint32_t b1 = b[nt >> 1][(nt & 1)*2 + 1];
                mma16(o[nt], a0, a1, a2, a3, b0, b1);
            }
        }
    }

    float inv0 = 1.0f / l0;
    float inv1 = 1.0f / l1;
    #pragma unroll
    for (int nt = 0; nt < 8; nt++) {
        int d = nt*8 + lq*2;
        size_t r0g = (size_t)(bb*SEQ + qt*QTILE + row0)*D_MODEL + h*64 + d;
        size_t r1g = (size_t)(bb*SEQ + qt*QTILE + row1)*D_MODEL + h*64 + d;
        *(uint32_t*)&g_attnh[r0g] = h2pack(o[nt][0]*inv0, o[nt][1]*inv0);
        *(uint32_t*)&g_attnh[r1g] = h2pack(o[nt][2]*inv1, o[nt][3]*inv1);
    }
}

// ===========================================================================
extern "C" void kernel_launch(void* const* d_in, const int* in_sizes, int n_in,
                              void* d_out, int out_size)
{
    const float* x     = (const float*)d_in[0];
    const float* w_qkv = (const float*)d_in[1];
    const float* b_qkv = (const float*)d_in[2];
    const float* w_out = (const float*)d_in[3];
    const float* b_out = (const float*)d_in[4];
    float* out = (float*)d_out;

    (void)in_sizes; (void)n_in; (void)out_size;

    cudaFuncSetAttribute(qkv_mma_kernel,
                         cudaFuncAttributeMaxDynamicSharedMemorySize, GEMM_SMEM_BYTES);
    cudaFuncSetAttribute(out_mma_kernel,
                         cudaFuncAttributeMaxDynamicSharedMemorySize, GEMM_SMEM_BYTES);
    cudaFuncSetAttribute(flash_mma_kernel,
                         cudaFuncAttributeMaxDynamicSharedMemorySize, FLASH_SMEM_BYTES);

    // 0) merged pre-pass (x cvt + weight transposes)
    prepass_kernel<<<PRE_BLOCKS, 256>>>(x, w_qkv, w_out);

    // 1) QKV GEMM
    {
        dim3 grid(NQKV/128, MTOT/128);
        qkv_mma_kernel<<<grid, 256, GEMM_SMEM_BYTES>>>(b_qkv);
    }
    // 2) flash attention
    {
        dim3 grid(SEQ/QTILE, NHEAD, BATCH);
        flash_mma_kernel<<<grid, 256, FLASH_SMEM_BYTES>>>();
    }
    // 3) out GEMM
    {
        dim3 grid(D_MODEL/128, MTOT/128);
        out_mma_kernel<<<grid, 256, GEMM_SMEM_BYTES>>>(b_out, out);
    }
}